// round 8
// baseline (speedup 1.0000x reference)
#include <cuda_runtime.h>

#define NN 50000
#define D 128
#define EE 800000

typedef unsigned long long ull;

// Scratch (device globals: allocation-free per harness rules)
__device__ __align__(16) float g_h[NN * D];
__device__ __align__(16) float g_x1[NN * D];
__device__ float g_deg[NN];
__device__ float g_dinv[NN];
__device__ int   g_cnt[NN];
__device__ int   g_cur[NN];
__device__ int   g_off[NN + 1];
__device__ int   g_csr_src[EE];
__device__ float g_csr_coef[EE];
__device__ int   g_detect = 0;                  // 0 => int64 edges, 1 => int32 (sticky)

// ---- packed f32x2 helpers (sm_103a) ---------------------------------------
__device__ __forceinline__ ull pk2(float a) {
    ull r; asm("mov.b64 %0, {%1, %1};" : "=l"(r) : "f"(a)); return r;
}
__device__ __forceinline__ void fma2(ull& d, ull a, ull b) {
    asm("fma.rn.f32x2 %0, %1, %2, %0;" : "+l"(d) : "l"(a), "l"(b));
}
__device__ __forceinline__ float2 unpk(ull a) {
    float2 r; asm("mov.b64 {%0, %1}, %2;" : "=f"(r.x), "=f"(r.y) : "l"(a)); return r;
}

__device__ __forceinline__ int ld_edge(const void* ei, long long pos, int is32) {
    if (is32) return ((const int*)ei)[pos];
    return (int)((const long long*)ei)[pos];
}

// ---------------------------------------------------------------------------
// Prep 1: counters + self-loop degree; block 0 probes edge dtype.
// ---------------------------------------------------------------------------
__global__ void prep_init_kernel(const int* __restrict__ ei32, int E, int n) {
    int i = blockIdx.x * blockDim.x + threadIdx.x;
    if (i < n) {
        g_deg[i] = 1.0f;
        g_cnt[i] = 0;
        g_cur[i] = 0;
    }
    if (blockIdx.x == 0) {
        int acc = 0;
        for (int k = threadIdx.x; k < 2048 && k < E; k += blockDim.x)
            acc |= ei32[2 * k + 1];
        if (acc) atomicOr(&g_detect, 1);
    }
}

// Prep 2: degree accumulate + dst histogram
__global__ void deg_hist_kernel(const void* __restrict__ ei,
                                const float* __restrict__ ew, int E, int n) {
    int e = blockIdx.x * blockDim.x + threadIdx.x;
    if (e < E) {
        int is32 = g_detect;
        int d = ld_edge(ei, (long long)E + e, is32);
        if ((unsigned)d >= (unsigned)n) return;
        atomicAdd(&g_deg[d], ew[e]);
        atomicAdd(&g_cnt[d], 1);
    }
}

// Prep 3: single-block scan of g_cnt -> g_off, fused dinv
__global__ void scan_kernel(int n) {
    __shared__ int s[1024];
    int t = threadIdx.x;
    int chunk = (n + 1023) >> 10;
    int start = t * chunk;
    int stop = min(start + chunk, n);

    int sum = 0;
    for (int i = start; i < stop; i++) sum += g_cnt[i];
    s[t] = sum;
    __syncthreads();

    for (int off = 1; off < 1024; off <<= 1) {
        int v = 0;
        if (t >= off) v = s[t - off];
        __syncthreads();
        if (t >= off) s[t] += v;
        __syncthreads();
    }

    int run = (t == 0) ? 0 : s[t - 1];
    for (int i = start; i < stop; i++) {
        g_off[i] = run;
        run += g_cnt[i];
        float dg = g_deg[i];
        g_dinv[i] = (dg > 0.0f) ? rsqrtf(dg) : 0.0f;
    }
    if (t == 1023) g_off[n] = s[1023];
}

// Prep 4: counting-sort scatter (separate arrays — measured best)
__global__ void scatter_kernel(const void* __restrict__ ei,
                               const float* __restrict__ ew, int E, int n) {
    int e = blockIdx.x * blockDim.x + threadIdx.x;
    if (e < E) {
        int is32 = g_detect;
        int s = ld_edge(ei, e, is32);
        int d = ld_edge(ei, (long long)E + e, is32);
        if ((unsigned)s >= (unsigned)n || (unsigned)d >= (unsigned)n) return;
        int pos = g_off[d] + atomicAdd(&g_cur[d], 1);
        g_csr_src[pos] = s;
        g_csr_coef[pos] = g_dinv[s] * ew[e] * g_dinv[d];
    }
}

// ---------------------------------------------------------------------------
// GEMM (measured-best layout): block 128 threads, 16 nodes, node range [off,end)
// ---------------------------------------------------------------------------
__global__ void gemm_kernel(const float* __restrict__ X,
                            const float* __restrict__ W, int off, int end) {
    __shared__ float xsT[D][20];  // [k][node], padded stride
    int node0 = off + blockIdx.x * 16;
    int t = threadIdx.x;

#pragma unroll
    for (int r = 0; r < 16; r++) {
        float v = (node0 + r < end) ? __ldg(X + (size_t)(node0 + r) * D + t) : 0.f;
        xsT[t][r] = v;
    }
    __syncthreads();

    int tx = t & 31;
    int tg = t >> 5;

    ull acc[4][2];
#pragma unroll
    for (int i = 0; i < 4; i++) { acc[i][0] = 0ull; acc[i][1] = 0ull; }

#pragma unroll 2
    for (int k = 0; k < D; k++) {
        longlong2 w2 = __ldg((const longlong2*)W + (size_t)k * 32 + tx);
        float4 xv = *(const float4*)&xsT[k][tg * 4];  // broadcast LDS.128
        ull wlo = (ull)w2.x, whi = (ull)w2.y;
        ull xp;
        xp = pk2(xv.x); fma2(acc[0][0], xp, wlo); fma2(acc[0][1], xp, whi);
        xp = pk2(xv.y); fma2(acc[1][0], xp, wlo); fma2(acc[1][1], xp, whi);
        xp = pk2(xv.z); fma2(acc[2][0], xp, wlo); fma2(acc[2][1], xp, whi);
        xp = pk2(xv.w); fma2(acc[3][0], xp, wlo); fma2(acc[3][1], xp, whi);
    }

#pragma unroll
    for (int i = 0; i < 4; i++) {
        int node = node0 + tg * 4 + i;
        if (node < end) {
            ulonglong2 v; v.x = acc[i][0]; v.y = acc[i][1];
            ((ulonglong2*)(g_h + (size_t)node * D))[tx] = v;
        }
    }
}

// ---------------------------------------------------------------------------
// Pull aggregation (measured-best loop): warp per dst node, lane owns 4 dims.
// ---------------------------------------------------------------------------
__device__ __forceinline__ void agg_core(int node, int lane, ull& a0, ull& a1) {
    int beg = g_off[node];
    int end = g_off[node + 1];
    const ulonglong2* hv = (const ulonglong2*)g_h;

    int j = beg;
    for (; j + 1 < end; j += 2) {
        int s0 = __ldg(&g_csr_src[j]);
        int s1 = __ldg(&g_csr_src[j + 1]);
        float c0 = __ldg(&g_csr_coef[j]);
        float c1 = __ldg(&g_csr_coef[j + 1]);
        ulonglong2 h0 = __ldg(hv + (size_t)s0 * 32 + lane);
        ulonglong2 h1 = __ldg(hv + (size_t)s1 * 32 + lane);
        ull cp0 = pk2(c0), cp1 = pk2(c1);
        fma2(a0, cp0, h0.x); fma2(a1, cp0, h0.y);
        fma2(a0, cp1, h1.x); fma2(a1, cp1, h1.y);
    }
    if (j < end) {
        int s0 = __ldg(&g_csr_src[j]);
        float c0 = __ldg(&g_csr_coef[j]);
        ulonglong2 h0 = __ldg(hv + (size_t)s0 * 32 + lane);
        ull cp0 = pk2(c0);
        fma2(a0, cp0, h0.x); fma2(a1, cp0, h0.y);
    }

    float sl = g_dinv[node];
    ull slp = pk2(sl * sl);
    ulonglong2 hs = hv[(size_t)node * 32 + lane];
    fma2(a0, slp, hs.x); fma2(a1, slp, hs.y);
}

__global__ void agg1_kernel(const float* __restrict__ b, int off, int end) {
    int node = off + blockIdx.x * 8 + (threadIdx.x >> 5);
    int lane = threadIdx.x & 31;
    if (node >= end) return;

    ull a0 = 0ull, a1 = 0ull;
    agg_core(node, lane, a0, a1);

    float2 p0 = unpk(a0), p1 = unpk(a1);
    float4 bias = __ldg((const float4*)b + lane);
    float4 v;
    v.x = fmaxf(p0.x + bias.x, 0.f);
    v.y = fmaxf(p0.y + bias.y, 0.f);
    v.z = fmaxf(p1.x + bias.z, 0.f);
    v.w = fmaxf(p1.y + bias.w, 0.f);
    ((float4*)g_x1)[(size_t)node * 32 + lane] = v;
}

__global__ void agg2_kernel(const float* __restrict__ b,
                            float* __restrict__ out, int n) {
    int node = blockIdx.x * 8 + (threadIdx.x >> 5);
    int lane = threadIdx.x & 31;
    if (node >= n) return;

    ull a0 = 0ull, a1 = 0ull;
    agg_core(node, lane, a0, a1);

    float2 p0 = unpk(a0), p1 = unpk(a1);
    float4 bias = __ldg((const float4*)b + lane);
    float4 v2;
    v2.x = fmaxf(p0.x + bias.x, 0.f);
    v2.y = fmaxf(p0.y + bias.y, 0.f);
    v2.z = fmaxf(p1.x + bias.z, 0.f);
    v2.w = fmaxf(p1.y + bias.w, 0.f);

    float4 v1 = ((const float4*)g_x1)[(size_t)node * 32 + lane];
    float4 lo = make_float4(v1.x, v2.x, v1.y, v2.y);
    float4 hi = make_float4(v1.z, v2.z, v1.w, v2.w);
    size_t o = (size_t)node * 64 + (size_t)lane * 2;
    ((float4*)out)[o] = lo;
    ((float4*)out)[o + 1] = hi;
}

// ---------------------------------------------------------------------------
extern "C" void kernel_launch(void* const* d_in, const int* in_sizes, int n_in,
                              void* d_out, int out_size) {
    const float* x = (const float*)d_in[0];
    const void* ei = d_in[1];
    const float* ew = (const float*)d_in[2];
    const float* W1 = (const float*)d_in[3];
    const float* b1 = (const float*)d_in[4];
    const float* W2 = (const float*)d_in[5];
    const float* b2 = (const float*)d_in[6];
    float* out = (float*)d_out;

    int n = in_sizes[0] / D;   // 50000
    int E = in_sizes[2];       // 800000
    int n2 = (n + 1) / 2;      // split point for agg1/gemm2 pipelining

    static cudaStream_t s2 = nullptr;
    static cudaEvent_t evRoot = nullptr, evPrep = nullptr, evG1 = nullptr,
                       evB = nullptr;
    static const float* x1_ptr = nullptr;
    if (!s2) {
        cudaStreamCreateWithFlags(&s2, cudaStreamNonBlocking);
        cudaEventCreateWithFlags(&evRoot, cudaEventDisableTiming);
        cudaEventCreateWithFlags(&evPrep, cudaEventDisableTiming);
        cudaEventCreateWithFlags(&evG1, cudaEventDisableTiming);
        cudaEventCreateWithFlags(&evB, cudaEventDisableTiming);
        void* p = nullptr;
        cudaGetSymbolAddress(&p, g_x1);
        x1_ptr = (const float*)p;
    }

    int tb = 256;
    int nodeBlocks = (n + tb - 1) / tb;
    int edgeBlocks = (E + tb - 1) / tb;

    // Fork point
    cudaEventRecord(evRoot, 0);

    // [launch 1] GEMM1 on default stream (full range)
    gemm_kernel<<<(n + 15) / 16, 128>>>(x, W1, 0, n);
    cudaEventRecord(evG1, 0);

    // Prep chain on s2 (concurrent with GEMM1): launches 2-5
    cudaStreamWaitEvent(s2, evRoot, 0);
    prep_init_kernel<<<nodeBlocks, tb, 0, s2>>>((const int*)ei, E, n);
    deg_hist_kernel<<<edgeBlocks, tb, 0, s2>>>(ei, ew, E, n);
    scan_kernel<<<1, 1024, 0, s2>>>(n);
    scatter_kernel<<<edgeBlocks, tb, 0, s2>>>(ei, ew, E, n);
    cudaEventRecord(evPrep, s2);

    // [launch 6] agg1 half A on default stream (profiled by ncu -s 5 -c 1)
    cudaStreamWaitEvent(0, evPrep, 0);
    agg1_kernel<<<(n2 + 7) / 8, tb>>>(b1, 0, n2);

    // [launch 7] agg1 half B on s2 (needs gemm1 + prep)
    cudaStreamWaitEvent(s2, evG1, 0);
    agg1_kernel<<<(n - n2 + 7) / 8, tb, 0, s2>>>(b1, n2, n);

    // [launch 8] gemm2 half A on default (overlaps agg1 half B on s2)
    gemm_kernel<<<(n2 + 15) / 16, 128>>>(x1_ptr, W2, 0, n2);

    // [launch 9] gemm2 half B on s2 (after agg1_B, same stream)
    gemm_kernel<<<(n - n2 + 15) / 16, 128, 0, s2>>>(x1_ptr, W2, n2, n);
    cudaEventRecord(evB, s2);

    // [launch 10] agg2 full, needs gemm2 A (same stream) + B (event)
    cudaStreamWaitEvent(0, evB, 0);
    agg2_kernel<<<(n + 7) / 8, tb>>>(b2, out, n);
}

// round 9
// speedup vs baseline: 1.7388x; 1.7388x over previous
#include <cuda_runtime.h>

#define NN 50000
#define D 128
#define EE 800000

typedef unsigned long long ull;

// Scratch (device globals: allocation-free per harness rules)
__device__ __align__(16) float g_h[NN * D];
__device__ __align__(16) float g_x1[NN * D];
__device__ float g_deg[NN];
__device__ float g_dinv[NN];
__device__ int   g_cnt[NN];
__device__ int   g_cur[NN];
__device__ int   g_off[NN];                     // segment start per node (unordered)
__device__ int   g_total;                       // segment allocator
__device__ int   g_csr_src[EE];
__device__ float g_csr_coef[EE];
__device__ int   g_detect = 0;                  // 0 => int64 edges, 1 => int32 (sticky)

// ---- packed f32x2 helpers (sm_103a) ---------------------------------------
__device__ __forceinline__ ull pk2(float a) {
    ull r; asm("mov.b64 %0, {%1, %1};" : "=l"(r) : "f"(a)); return r;
}
__device__ __forceinline__ void fma2(ull& d, ull a, ull b) {
    asm("fma.rn.f32x2 %0, %1, %2, %0;" : "+l"(d) : "l"(a), "l"(b));
}
__device__ __forceinline__ float2 unpk(ull a) {
    float2 r; asm("mov.b64 {%0, %1}, %2;" : "=f"(r.x), "=f"(r.y) : "l"(a)); return r;
}

__device__ __forceinline__ int ld_edge(const void* ei, long long pos, int is32) {
    if (is32) return ((const int*)ei)[pos];
    return (int)((const long long*)ei)[pos];
}

// ---------------------------------------------------------------------------
// Prep 1: counters + self-loop degree; block 0 probes edge dtype.
// ---------------------------------------------------------------------------
__global__ void prep_init_kernel(const int* __restrict__ ei32, int E, int n) {
    int i = blockIdx.x * blockDim.x + threadIdx.x;
    if (i < n) {
        g_deg[i] = 1.0f;
        g_cnt[i] = 0;
        g_cur[i] = 0;
    }
    if (i == 0) g_total = 0;
    if (blockIdx.x == 0) {
        int acc = 0;
        for (int k = threadIdx.x; k < 2048 && k < E; k += blockDim.x)
            acc |= ei32[2 * k + 1];
        if (acc) atomicOr(&g_detect, 1);
    }
}

// Prep 2: degree accumulate + dst histogram
__global__ void deg_hist_kernel(const void* __restrict__ ei,
                                const float* __restrict__ ew, int E, int n) {
    int e = blockIdx.x * blockDim.x + threadIdx.x;
    if (e < E) {
        int is32 = g_detect;
        int d = ld_edge(ei, (long long)E + e, is32);
        if ((unsigned)d >= (unsigned)n) return;
        atomicAdd(&g_deg[d], ew[e]);
        atomicAdd(&g_cnt[d], 1);
    }
}

// Prep 3: segment allocation (NO scan — order doesn't matter) + dinv.
// Single uniform-address atomic per thread: ptxas aggregates per warp (REDUX).
__global__ void offsets_kernel(int n) {
    int i = blockIdx.x * blockDim.x + threadIdx.x;
    if (i < n) {
        int cnt = g_cnt[i];
        g_off[i] = atomicAdd(&g_total, cnt);
        float dg = g_deg[i];
        g_dinv[i] = (dg > 0.0f) ? rsqrtf(dg) : 0.0f;
    }
}

// Prep 4: counting-sort scatter into per-dst segments
__global__ void scatter_kernel(const void* __restrict__ ei,
                               const float* __restrict__ ew, int E, int n) {
    int e = blockIdx.x * blockDim.x + threadIdx.x;
    if (e < E) {
        int is32 = g_detect;
        int s = ld_edge(ei, e, is32);
        int d = ld_edge(ei, (long long)E + e, is32);
        if ((unsigned)s >= (unsigned)n || (unsigned)d >= (unsigned)n) return;
        int pos = g_off[d] + atomicAdd(&g_cur[d], 1);
        g_csr_src[pos] = s;
        g_csr_coef[pos] = g_dinv[s] * ew[e] * g_dinv[d];
    }
}

// ---------------------------------------------------------------------------
// GEMM (measured-best layout): block 128 threads, 16 nodes.
// ---------------------------------------------------------------------------
__global__ void gemm_kernel(const float* __restrict__ X,
                            const float* __restrict__ W, int n) {
    __shared__ float xsT[D][20];  // [k][node], padded stride
    int node0 = blockIdx.x * 16;
    int t = threadIdx.x;

#pragma unroll
    for (int r = 0; r < 16; r++) {
        float v = (node0 + r < n) ? __ldg(X + (size_t)(node0 + r) * D + t) : 0.f;
        xsT[t][r] = v;
    }
    __syncthreads();

    int tx = t & 31;
    int tg = t >> 5;

    ull acc[4][2];
#pragma unroll
    for (int i = 0; i < 4; i++) { acc[i][0] = 0ull; acc[i][1] = 0ull; }

#pragma unroll 2
    for (int k = 0; k < D; k++) {
        longlong2 w2 = __ldg((const longlong2*)W + (size_t)k * 32 + tx);
        float4 xv = *(const float4*)&xsT[k][tg * 4];  // broadcast LDS.128
        ull wlo = (ull)w2.x, whi = (ull)w2.y;
        ull xp;
        xp = pk2(xv.x); fma2(acc[0][0], xp, wlo); fma2(acc[0][1], xp, whi);
        xp = pk2(xv.y); fma2(acc[1][0], xp, wlo); fma2(acc[1][1], xp, whi);
        xp = pk2(xv.z); fma2(acc[2][0], xp, wlo); fma2(acc[2][1], xp, whi);
        xp = pk2(xv.w); fma2(acc[3][0], xp, wlo); fma2(acc[3][1], xp, whi);
    }

#pragma unroll
    for (int i = 0; i < 4; i++) {
        int node = node0 + tg * 4 + i;
        if (node < n) {
            ulonglong2 v; v.x = acc[i][0]; v.y = acc[i][1];
            ((ulonglong2*)(g_h + (size_t)node * D))[tx] = v;
        }
    }
}

// ---------------------------------------------------------------------------
// Pull aggregation (measured-best loop): warp per dst node, lane owns 4 dims.
// Segment = [g_off[node], g_off[node] + g_cnt[node]).
// ---------------------------------------------------------------------------
__device__ __forceinline__ void agg_core(int node, int lane, ull& a0, ull& a1) {
    int beg = g_off[node];
    int end = beg + g_cnt[node];
    const ulonglong2* hv = (const ulonglong2*)g_h;

    int j = beg;
    for (; j + 1 < end; j += 2) {
        int s0 = __ldg(&g_csr_src[j]);
        int s1 = __ldg(&g_csr_src[j + 1]);
        float c0 = __ldg(&g_csr_coef[j]);
        float c1 = __ldg(&g_csr_coef[j + 1]);
        ulonglong2 h0 = __ldg(hv + (size_t)s0 * 32 + lane);
        ulonglong2 h1 = __ldg(hv + (size_t)s1 * 32 + lane);
        ull cp0 = pk2(c0), cp1 = pk2(c1);
        fma2(a0, cp0, h0.x); fma2(a1, cp0, h0.y);
        fma2(a0, cp1, h1.x); fma2(a1, cp1, h1.y);
    }
    if (j < end) {
        int s0 = __ldg(&g_csr_src[j]);
        float c0 = __ldg(&g_csr_coef[j]);
        ulonglong2 h0 = __ldg(hv + (size_t)s0 * 32 + lane);
        ull cp0 = pk2(c0);
        fma2(a0, cp0, h0.x); fma2(a1, cp0, h0.y);
    }

    float sl = g_dinv[node];
    ull slp = pk2(sl * sl);
    ulonglong2 hs = hv[(size_t)node * 32 + lane];
    fma2(a0, slp, hs.x); fma2(a1, slp, hs.y);
}

__global__ void agg1_kernel(const float* __restrict__ b, int n) {
    int node = blockIdx.x * 8 + (threadIdx.x >> 5);
    int lane = threadIdx.x & 31;
    if (node >= n) return;

    ull a0 = 0ull, a1 = 0ull;
    agg_core(node, lane, a0, a1);

    float2 p0 = unpk(a0), p1 = unpk(a1);
    float4 bias = __ldg((const float4*)b + lane);
    float4 v;
    v.x = fmaxf(p0.x + bias.x, 0.f);
    v.y = fmaxf(p0.y + bias.y, 0.f);
    v.z = fmaxf(p1.x + bias.z, 0.f);
    v.w = fmaxf(p1.y + bias.w, 0.f);
    ((float4*)g_x1)[(size_t)node * 32 + lane] = v;
}

__global__ void agg2_kernel(const float* __restrict__ b,
                            float* __restrict__ out, int n) {
    int node = blockIdx.x * 8 + (threadIdx.x >> 5);
    int lane = threadIdx.x & 31;
    if (node >= n) return;

    ull a0 = 0ull, a1 = 0ull;
    agg_core(node, lane, a0, a1);

    float2 p0 = unpk(a0), p1 = unpk(a1);
    float4 bias = __ldg((const float4*)b + lane);
    float4 v2;
    v2.x = fmaxf(p0.x + bias.x, 0.f);
    v2.y = fmaxf(p0.y + bias.y, 0.f);
    v2.z = fmaxf(p1.x + bias.z, 0.f);
    v2.w = fmaxf(p1.y + bias.w, 0.f);

    float4 v1 = ((const float4*)g_x1)[(size_t)node * 32 + lane];
    float4 lo = make_float4(v1.x, v2.x, v1.y, v2.y);
    float4 hi = make_float4(v1.z, v2.z, v1.w, v2.w);
    size_t o = (size_t)node * 64 + (size_t)lane * 2;
    ((float4*)out)[o] = lo;
    ((float4*)out)[o + 1] = hi;
}

// ---------------------------------------------------------------------------
extern "C" void kernel_launch(void* const* d_in, const int* in_sizes, int n_in,
                              void* d_out, int out_size) {
    const float* x = (const float*)d_in[0];
    const void* ei = d_in[1];
    const float* ew = (const float*)d_in[2];
    const float* W1 = (const float*)d_in[3];
    const float* b1 = (const float*)d_in[4];
    const float* W2 = (const float*)d_in[5];
    const float* b2 = (const float*)d_in[6];
    float* out = (float*)d_out;

    int n = in_sizes[0] / D;   // 50000
    int E = in_sizes[2];       // 800000

    static cudaStream_t s2 = nullptr;
    static cudaEvent_t evRoot = nullptr, evPrep = nullptr;
    static const float* x1_ptr = nullptr;
    if (!s2) {
        cudaStreamCreateWithFlags(&s2, cudaStreamNonBlocking);
        cudaEventCreateWithFlags(&evRoot, cudaEventDisableTiming);
        cudaEventCreateWithFlags(&evPrep, cudaEventDisableTiming);
        void* p = nullptr;
        cudaGetSymbolAddress(&p, g_x1);
        x1_ptr = (const float*)p;
    }

    int tb = 256;
    int nodeBlocks = (n + tb - 1) / tb;
    int edgeBlocks = (E + tb - 1) / tb;
    int gemmBlocks = (n + 15) / 16;
    int aggBlocks = (n + 7) / 8;

    // Fork point
    cudaEventRecord(evRoot, 0);

    // [launch 1] GEMM1 on default stream
    gemm_kernel<<<gemmBlocks, 128>>>(x, W1, n);

    // Prep chain on s2 (concurrent with GEMM1): launches 2-5
    cudaStreamWaitEvent(s2, evRoot, 0);
    prep_init_kernel<<<nodeBlocks, tb, 0, s2>>>((const int*)ei, E, n);
    deg_hist_kernel<<<edgeBlocks, tb, 0, s2>>>(ei, ew, E, n);
    offsets_kernel<<<nodeBlocks, tb, 0, s2>>>(n);
    scatter_kernel<<<edgeBlocks, tb, 0, s2>>>(ei, ew, E, n);
    cudaEventRecord(evPrep, s2);

    // Join, then sequential main path: launches 6-8 (ncu -s 5 profiles agg1)
    cudaStreamWaitEvent(0, evPrep, 0);
    agg1_kernel<<<aggBlocks, tb>>>(b1, n);
    gemm_kernel<<<gemmBlocks, 128>>>(x1_ptr, W2, n);
    agg2_kernel<<<aggBlocks, tb>>>(b2, out, n);
}

// round 10
// speedup vs baseline: 1.9067x; 1.0966x over previous
#include <cuda_runtime.h>
#include <cuda_fp16.h>

#define NN 50000
#define D 128
#define EE 800000

typedef unsigned long long ull;

// Scratch (device globals: allocation-free; zero-initialized at module load,
// and each kernel restores the zero-state after last use so graph replays
// see identical initial conditions).
__device__ __align__(16) __half g_h[NN * D];    // fp16 features (both layers)
__device__ __align__(16) float g_x1[NN * D];    // layer-1 activations (f32)
__device__ float g_deg[NN];                     // edge-weight sums (excl. self loop)
__device__ float g_dinv[NN];
__device__ int   g_cnt[NN];
__device__ int   g_cur[NN];
__device__ int   g_off[NN];                     // segment start per node (unordered)
__device__ int   g_total;                       // segment allocator
__device__ int   g_csr_src[EE];
__device__ float g_csr_coef[EE];
__device__ int   g_detect = 0;                  // 0 => int64 edges, 1 => int32 (sticky)

// ---- packed f32x2 helpers (sm_103a) ---------------------------------------
__device__ __forceinline__ ull pk2(float a) {
    ull r; asm("mov.b64 %0, {%1, %1};" : "=l"(r) : "f"(a)); return r;
}
__device__ __forceinline__ ull pkf2(float2 a) {
    ull r; asm("mov.b64 %0, {%1, %2};" : "=l"(r) : "f"(a.x), "f"(a.y)); return r;
}
__device__ __forceinline__ void fma2(ull& d, ull a, ull b) {
    asm("fma.rn.f32x2 %0, %1, %2, %0;" : "+l"(d) : "l"(a), "l"(b));
}
__device__ __forceinline__ float2 unpk(ull a) {
    float2 r; asm("mov.b64 {%0, %1}, %2;" : "=f"(r.x), "=f"(r.y) : "l"(a)); return r;
}

// fp16x4 (one ull) -> two packed f32x2 operands
__device__ __forceinline__ void h4_to_f2x2(ull h, ull& lo, ull& hi) {
    unsigned int ulo = (unsigned int)h;
    unsigned int uhi = (unsigned int)(h >> 32);
    float2 flo = __half22float2(*reinterpret_cast<__half2*>(&ulo));
    float2 fhi = __half22float2(*reinterpret_cast<__half2*>(&uhi));
    lo = pkf2(flo);
    hi = pkf2(fhi);
}

__device__ __forceinline__ int ld_edge(const void* ei, long long pos, int is32) {
    if (is32) return ((const int*)ei)[pos];
    return (int)((const long long*)ei)[pos];
}

// ---------------------------------------------------------------------------
// Prep 1: edge-dtype probe (sticky; idempotent across replays)
// ---------------------------------------------------------------------------
__global__ void detect_kernel(const int* __restrict__ ei32, int E) {
    int acc = 0;
    for (int k = threadIdx.x; k < 2048 && k < E; k += blockDim.x)
        acc |= ei32[2 * k + 1];
    if (acc) atomicOr(&g_detect, 1);
}

// Prep 2: degree accumulate + dst histogram (counters start at zero)
__global__ void deg_hist_kernel(const void* __restrict__ ei,
                                const float* __restrict__ ew, int E, int n) {
    int e = blockIdx.x * blockDim.x + threadIdx.x;
    if (e < E) {
        int is32 = g_detect;
        int d = ld_edge(ei, (long long)E + e, is32);
        if ((unsigned)d >= (unsigned)n) return;
        atomicAdd(&g_deg[d], ew[e]);
        atomicAdd(&g_cnt[d], 1);
    }
}

// Prep 3: segment allocation + dinv (self-loop weight 1 folded in: deg_sum+1).
// Resets g_deg for the next replay after last use.
__global__ void offsets_kernel(int n) {
    int i = blockIdx.x * blockDim.x + threadIdx.x;
    if (i < n) {
        int cnt = g_cnt[i];
        g_off[i] = atomicAdd(&g_total, cnt);
        g_dinv[i] = rsqrtf(g_deg[i] + 1.0f);
        g_deg[i] = 0.0f;   // restore zero-state
    }
}

// Prep 4: counting-sort scatter into per-dst segments
__global__ void scatter_kernel(const void* __restrict__ ei,
                               const float* __restrict__ ew, int E, int n) {
    int e = blockIdx.x * blockDim.x + threadIdx.x;
    if (e < E) {
        int is32 = g_detect;
        int s = ld_edge(ei, e, is32);
        int d = ld_edge(ei, (long long)E + e, is32);
        if ((unsigned)s >= (unsigned)n || (unsigned)d >= (unsigned)n) return;
        int pos = g_off[d] + atomicAdd(&g_cur[d], 1);
        g_csr_src[pos] = s;
        g_csr_coef[pos] = g_dinv[s] * ew[e] * g_dinv[d];
    }
}

// ---------------------------------------------------------------------------
// GEMM: g_h(fp16) = X(f32) * W. Block 128 threads, 16 nodes (measured-best).
// ---------------------------------------------------------------------------
__global__ void gemm_kernel(const float* __restrict__ X,
                            const float* __restrict__ W, int n) {
    __shared__ float xsT[D][20];  // [k][node], padded stride
    int node0 = blockIdx.x * 16;
    int t = threadIdx.x;

#pragma unroll
    for (int r = 0; r < 16; r++) {
        float v = (node0 + r < n) ? __ldg(X + (size_t)(node0 + r) * D + t) : 0.f;
        xsT[t][r] = v;
    }
    __syncthreads();

    int tx = t & 31;
    int tg = t >> 5;

    ull acc[4][2];
#pragma unroll
    for (int i = 0; i < 4; i++) { acc[i][0] = 0ull; acc[i][1] = 0ull; }

#pragma unroll 2
    for (int k = 0; k < D; k++) {
        longlong2 w2 = __ldg((const longlong2*)W + (size_t)k * 32 + tx);
        float4 xv = *(const float4*)&xsT[k][tg * 4];  // broadcast LDS.128
        ull wlo = (ull)w2.x, whi = (ull)w2.y;
        ull xp;
        xp = pk2(xv.x); fma2(acc[0][0], xp, wlo); fma2(acc[0][1], xp, whi);
        xp = pk2(xv.y); fma2(acc[1][0], xp, wlo); fma2(acc[1][1], xp, whi);
        xp = pk2(xv.z); fma2(acc[2][0], xp, wlo); fma2(acc[2][1], xp, whi);
        xp = pk2(xv.w); fma2(acc[3][0], xp, wlo); fma2(acc[3][1], xp, whi);
    }

#pragma unroll
    for (int i = 0; i < 4; i++) {
        int node = node0 + tg * 4 + i;
        if (node < n) {
            float2 p0 = unpk(acc[i][0]);
            float2 p1 = unpk(acc[i][1]);
            __half2 h0 = __floats2half2_rn(p0.x, p0.y);
            __half2 h1 = __floats2half2_rn(p1.x, p1.y);
            uint2 v;
            v.x = *reinterpret_cast<unsigned int*>(&h0);
            v.y = *reinterpret_cast<unsigned int*>(&h1);
            ((uint2*)(g_h + (size_t)node * D))[tx] = v;
        }
    }
}

// ---------------------------------------------------------------------------
// Pull aggregation: warp per dst node, lane owns 4 dims (fp16 gather, f32 acc)
// ---------------------------------------------------------------------------
__device__ __forceinline__ void agg_core(int node, int lane, ull& a0, ull& a1) {
    int beg = g_off[node];
    int end = beg + g_cnt[node];
    const ull* hv = (const ull*)g_h;   // 4 halves per lane slot

    int j = beg;
    for (; j + 1 < end; j += 2) {
        int s0 = __ldg(&g_csr_src[j]);
        int s1 = __ldg(&g_csr_src[j + 1]);
        float c0 = __ldg(&g_csr_coef[j]);
        float c1 = __ldg(&g_csr_coef[j + 1]);
        ull h0 = __ldg(hv + (size_t)s0 * 32 + lane);
        ull h1 = __ldg(hv + (size_t)s1 * 32 + lane);
        ull l0, u0, l1, u1;
        h4_to_f2x2(h0, l0, u0);
        h4_to_f2x2(h1, l1, u1);
        ull cp0 = pk2(c0), cp1 = pk2(c1);
        fma2(a0, cp0, l0); fma2(a1, cp0, u0);
        fma2(a0, cp1, l1); fma2(a1, cp1, u1);
    }
    if (j < end) {
        int s0 = __ldg(&g_csr_src[j]);
        float c0 = __ldg(&g_csr_coef[j]);
        ull h0 = __ldg(hv + (size_t)s0 * 32 + lane);
        ull l0, u0;
        h4_to_f2x2(h0, l0, u0);
        ull cp0 = pk2(c0);
        fma2(a0, cp0, l0); fma2(a1, cp0, u0);
    }

    // self-loop: + dinv^2 * h[node]
    float sl = g_dinv[node];
    ull slp = pk2(sl * sl);
    ull hs = hv[(size_t)node * 32 + lane];
    ull ls, us;
    h4_to_f2x2(hs, ls, us);
    fma2(a0, slp, ls); fma2(a1, slp, us);
}

__global__ void agg1_kernel(const float* __restrict__ b, int n) {
    int node = blockIdx.x * 8 + (threadIdx.x >> 5);
    int lane = threadIdx.x & 31;
    if (node >= n) return;

    ull a0 = 0ull, a1 = 0ull;
    agg_core(node, lane, a0, a1);

    if (lane == 0) g_cur[node] = 0;   // restore zero-state (last use was scatter)

    float2 p0 = unpk(a0), p1 = unpk(a1);
    float4 bias = __ldg((const float4*)b + lane);
    float4 v;
    v.x = fmaxf(p0.x + bias.x, 0.f);
    v.y = fmaxf(p0.y + bias.y, 0.f);
    v.z = fmaxf(p1.x + bias.z, 0.f);
    v.w = fmaxf(p1.y + bias.w, 0.f);
    ((float4*)g_x1)[(size_t)node * 32 + lane] = v;
}

__global__ void agg2_kernel(const float* __restrict__ b,
                            float* __restrict__ out, int n) {
    int node = blockIdx.x * 8 + (threadIdx.x >> 5);
    int lane = threadIdx.x & 31;
    if (node >= n) return;

    ull a0 = 0ull, a1 = 0ull;
    agg_core(node, lane, a0, a1);

    // restore zero-state for next replay (after last use of g_cnt)
    if (lane == 0) {
        g_cnt[node] = 0;
        if (node == 0) g_total = 0;
    }

    float2 p0 = unpk(a0), p1 = unpk(a1);
    float4 bias = __ldg((const float4*)b + lane);
    float4 v2;
    v2.x = fmaxf(p0.x + bias.x, 0.f);
    v2.y = fmaxf(p0.y + bias.y, 0.f);
    v2.z = fmaxf(p1.x + bias.z, 0.f);
    v2.w = fmaxf(p1.y + bias.w, 0.f);

    float4 v1 = ((const float4*)g_x1)[(size_t)node * 32 + lane];
    float4 lo = make_float4(v1.x, v2.x, v1.y, v2.y);
    float4 hi = make_float4(v1.z, v2.z, v1.w, v2.w);
    size_t o = (size_t)node * 64 + (size_t)lane * 2;
    ((float4*)out)[o] = lo;
    ((float4*)out)[o + 1] = hi;
}

// ---------------------------------------------------------------------------
extern "C" void kernel_launch(void* const* d_in, const int* in_sizes, int n_in,
                              void* d_out, int out_size) {
    const float* x = (const float*)d_in[0];
    const void* ei = d_in[1];
    const float* ew = (const float*)d_in[2];
    const float* W1 = (const float*)d_in[3];
    const float* b1 = (const float*)d_in[4];
    const float* W2 = (const float*)d_in[5];
    const float* b2 = (const float*)d_in[6];
    float* out = (float*)d_out;

    int n = in_sizes[0] / D;   // 50000
    int E = in_sizes[2];       // 800000

    static cudaStream_t s2 = nullptr;
    static cudaEvent_t evRoot = nullptr, evPrep = nullptr;
    static const float* x1_ptr = nullptr;
    if (!s2) {
        cudaStreamCreateWithFlags(&s2, cudaStreamNonBlocking);
        cudaEventCreateWithFlags(&evRoot, cudaEventDisableTiming);
        cudaEventCreateWithFlags(&evPrep, cudaEventDisableTiming);
        void* p = nullptr;
        cudaGetSymbolAddress(&p, g_x1);
        x1_ptr = (const float*)p;
    }

    int tb = 256;
    int nodeBlocks = (n + tb - 1) / tb;
    int edgeBlocks = (E + tb - 1) / tb;
    int gemmBlocks = (n + 15) / 16;
    int aggBlocks = (n + 7) / 8;

    // Fork point
    cudaEventRecord(evRoot, 0);

    // [1] GEMM1 on default stream
    gemm_kernel<<<gemmBlocks, 128>>>(x, W1, n);

    // Prep chain on s2 (concurrent with GEMM1): [2-5]
    cudaStreamWaitEvent(s2, evRoot, 0);
    detect_kernel<<<1, 256, 0, s2>>>((const int*)ei, E);
    deg_hist_kernel<<<edgeBlocks, tb, 0, s2>>>(ei, ew, E, n);
    offsets_kernel<<<nodeBlocks, tb, 0, s2>>>(n);
    scatter_kernel<<<edgeBlocks, tb, 0, s2>>>(ei, ew, E, n);
    cudaEventRecord(evPrep, s2);

    // Join, then sequential main path: [6-8]
    cudaStreamWaitEvent(0, evPrep, 0);
    agg1_kernel<<<aggBlocks, tb>>>(b1, n);
    gemm_kernel<<<gemmBlocks, 128>>>(x1_ptr, W2, n);
    agg2_kernel<<<aggBlocks, tb>>>(b2, out, n);
}